// round 10
// baseline (speedup 1.0000x reference)
#include <cuda_runtime.h>
#include <math.h>

// ---------------- problem constants ----------------
#define BT    16          // b*t frames
#define HH    40
#define WW    40
#define CC    128
#define NTOK  (BT*HH*WW)  // 25600
#define MFF   512
#define HEADS 4
#define DH    32
#define KNB   7
#define KK2   49
#define SPA   (8*HH*WW)   // 12800 spatial per batch-b

// ---------------- scratch (device globals; no allocations) ----------------
__device__ float g_h   [NTOK*CC];   // running hidden state
__device__ float g_ln  [NTOK*CC];   // layernorm output / staging
__device__ float g_qkv [NTOK*3*CC];
__device__ float g_att [NTOK*CC];
__device__ float g_f1  [NTOK*MFF];
__device__ float g_f2  [NTOK*MFF];

// ---------------- transpose in: x(B=2,C=128,T*H*W=12800) -> h(tok,C) ----------------
__global__ void k_transpose_in(const float* __restrict__ x, float* __restrict__ h)
{
    __shared__ float tile[32][33];
    int b  = blockIdx.z;
    int s0 = blockIdx.x * 32;
    int c0 = blockIdx.y * 32;
    int tx = threadIdx.x, ty = threadIdx.y;
#pragma unroll
    for (int i = 0; i < 32; i += 8)
        tile[ty + i][tx] = x[(size_t)(b*CC + c0 + ty + i) * SPA + s0 + tx];
    __syncthreads();
#pragma unroll
    for (int i = 0; i < 32; i += 8)
        h[(size_t)(b*SPA + s0 + ty + i) * CC + c0 + tx] = tile[tx][ty + i];
}

// ---------------- transpose out: h(tok,C) -> out(B,C,T*H*W) ----------------
__global__ void k_transpose_out(const float* __restrict__ h, float* __restrict__ out)
{
    __shared__ float tile[32][33];
    int b  = blockIdx.z;
    int s0 = blockIdx.x * 32;
    int c0 = blockIdx.y * 32;
    int tx = threadIdx.x, ty = threadIdx.y;
#pragma unroll
    for (int i = 0; i < 32; i += 8)
        tile[ty + i][tx] = h[(size_t)(b*SPA + s0 + ty + i) * CC + c0 + tx];
    __syncthreads();
#pragma unroll
    for (int i = 0; i < 32; i += 8)
        out[(size_t)(b*CC + c0 + ty + i) * SPA + s0 + tx] = tile[tx][ty + i];
}

// ---------------- per-token layernorm over C=128 ----------------
__global__ void k_layernorm(const float* __restrict__ in,
                            const float* __restrict__ g,
                            const float* __restrict__ b,
                            float* __restrict__ out)
{
    int tok = blockIdx.x;
    int c   = threadIdx.x;          // 128 threads
    float v = in[(size_t)tok*CC + c];
    float s = v, q = v*v;
#pragma unroll
    for (int o = 16; o > 0; o >>= 1) {
        s += __shfl_xor_sync(0xffffffffu, s, o);
        q += __shfl_xor_sync(0xffffffffu, q, o);
    }
    __shared__ float sh[8];
    int wid = c >> 5, lane = c & 31;
    if (lane == 0) { sh[wid] = s; sh[4+wid] = q; }
    __syncthreads();
    s = sh[0]+sh[1]+sh[2]+sh[3];
    q = sh[4]+sh[5]+sh[6]+sh[7];
    float mean = s * (1.0f/CC);
    float var  = q * (1.0f/CC) - mean*mean;
    float r    = rsqrtf(var + 1e-5f);
    out[(size_t)tok*CC + c] = (v - mean) * r * g[c] + b[c];
}

// ---------------- SGEMM: C[M,N] = A[M,K] @ B[K,N] + bias (+res) ----------------
// BM=BN=64, BK=16, 256 threads (16x16), 4x4 microtile. M%64==0, N%64==0, K%16==0.
template<bool RES>
__global__ void k_sgemm(const float* __restrict__ A, const float* __restrict__ B,
                        const float* __restrict__ bias, const float* __restrict__ res,
                        float* __restrict__ C, int M, int N, int K)
{
    __shared__ float As[16][65];   // [k][row], padded -> conflict-free stores/reads
    __shared__ float Bs[16][64];   // [k][col]
    int tid  = threadIdx.y * 16 + threadIdx.x;
    int row0 = blockIdx.y * 64;
    int col0 = blockIdx.x * 64;

    int aRow = tid >> 4;     // 0..15
    int aCol = tid & 15;     // 0..15
    int bRow = tid >> 6;     // 0..3
    int bCol = tid & 63;     // 0..63

    float acc[4][4];
#pragma unroll
    for (int i = 0; i < 4; i++)
#pragma unroll
        for (int j = 0; j < 4; j++) acc[i][j] = 0.0f;

    for (int k0 = 0; k0 < K; k0 += 16) {
#pragma unroll
        for (int i = 0; i < 4; i++)
            As[aCol][aRow + i*16] = A[(size_t)(row0 + aRow + i*16) * K + k0 + aCol];
#pragma unroll
        for (int i = 0; i < 4; i++)
            Bs[bRow + i*4][bCol]  = B[(size_t)(k0 + bRow + i*4) * N + col0 + bCol];
        __syncthreads();
#pragma unroll
        for (int kk = 0; kk < 16; kk++) {
            float a[4], bb[4];
#pragma unroll
            for (int i = 0; i < 4; i++) a[i]  = As[kk][threadIdx.y*4 + i];
#pragma unroll
            for (int j = 0; j < 4; j++) bb[j] = Bs[kk][threadIdx.x*4 + j];
#pragma unroll
            for (int i = 0; i < 4; i++)
#pragma unroll
                for (int j = 0; j < 4; j++)
                    acc[i][j] += a[i] * bb[j];
        }
        __syncthreads();
    }
#pragma unroll
    for (int i = 0; i < 4; i++) {
        int r = row0 + threadIdx.y*4 + i;
#pragma unroll
        for (int j = 0; j < 4; j++) {
            int c = col0 + threadIdx.x*4 + j;
            float v = acc[i][j] + bias[c];
            if (RES) v += res[(size_t)r * N + c];
            C[(size_t)r * N + c] = v;
        }
    }
}

// ---------------- neighborhood attention (k=7, heads=4, dh=32) ----------------
// one block per token, one warp per head; lane = head-dim d
__global__ void k_attn(const float* __restrict__ qkv,
                       const float* __restrict__ rpb,   // [4][13][13] for this layer
                       float* __restrict__ out)
{
    int tok  = blockIdx.x;
    int head = threadIdx.x >> 5;
    int lane = threadIdx.x & 31;
    int x  = tok % WW;
    int y  = (tok / WW) % HH;
    int bt = tok / (HH*WW);

    __shared__ float s_log[HEADS][KK2];

    int sy = min(max(y - 3, 0), HH - KNB);
    int sx = min(max(x - 3, 0), WW - KNB);

    float q = qkv[(size_t)tok*384 + head*DH + lane] * 0.17677669529663687f; // dh^-0.5

    // logits
    for (int i = 0; i < KNB; i++) {
        int iy = sy + i;
        int rowbase = (bt*HH + iy) * WW;
        int rh = iy - y + 6;
#pragma unroll
        for (int j = 0; j < KNB; j++) {
            int ix = sx + j;
            int kt = rowbase + ix;
            float p = q * qkv[(size_t)kt*384 + CC + head*DH + lane];
#pragma unroll
            for (int o = 16; o > 0; o >>= 1) p += __shfl_xor_sync(0xffffffffu, p, o);
            if (lane == 0) {
                float bias = rpb[(head*13 + rh)*13 + (ix - x + 6)];
                s_log[head][i*KNB + j] = p + bias;
            }
        }
    }
    __syncwarp();

    // softmax over 49 (each lane handles j and j+32)
    float l0 = s_log[head][lane];
    float l1 = (lane + 32 < KK2) ? s_log[head][lane + 32] : -1e30f;
    float m = fmaxf(l0, l1);
#pragma unroll
    for (int o = 16; o > 0; o >>= 1) m = fmaxf(m, __shfl_xor_sync(0xffffffffu, m, o));
    float e0 = expf(l0 - m);
    float e1 = (lane + 32 < KK2) ? expf(l1 - m) : 0.0f;
    float s = e0 + e1;
#pragma unroll
    for (int o = 16; o > 0; o >>= 1) s += __shfl_xor_sync(0xffffffffu, s, o);
    float inv = 1.0f / s;
    s_log[head][lane] = e0 * inv;
    if (lane + 32 < KK2) s_log[head][lane + 32] = e1 * inv;
    __syncwarp();

    // weighted sum over v
    float acc = 0.0f;
    for (int i = 0; i < KNB; i++) {
        int rowbase = (bt*HH + sy + i) * WW;
#pragma unroll
        for (int j = 0; j < KNB; j++) {
            int kt = rowbase + sx + j;
            acc += s_log[head][i*KNB + j] * qkv[(size_t)kt*384 + 2*CC + head*DH + lane];
        }
    }
    out[(size_t)tok*CC + head*DH + lane] = acc;
}

// ---------------- depthwise 3x3x3 conv (SAME, over t,y,x) + exact GELU ----------------
__global__ void k_dwconv_gelu(const float* __restrict__ in,
                              const float* __restrict__ w,    // [3][3][3][1][512]
                              const float* __restrict__ bias, // [512]
                              float* __restrict__ out)
{
    int e = blockIdx.x * blockDim.x + threadIdx.x;
    if (e >= NTOK * MFF) return;
    int m   = e & (MFF - 1);
    int tok = e >> 9;
    int x  = tok % WW;
    int y  = (tok / WW) % HH;
    int bt = tok / (HH*WW);
    int b  = bt >> 3;
    int t  = bt & 7;

    float acc = bias[m];
#pragma unroll
    for (int kd = 0; kd < 3; kd++) {
        int tt = t + kd - 1;
        if (tt < 0 || tt > 7) continue;
#pragma unroll
        for (int kh = 0; kh < 3; kh++) {
            int yy = y + kh - 1;
            if (yy < 0 || yy >= HH) continue;
#pragma unroll
            for (int kw = 0; kw < 3; kw++) {
                int xx = x + kw - 1;
                if (xx < 0 || xx >= WW) continue;
                size_t idx = ((size_t)((b*8 + tt)*HH + yy) * WW + xx) * MFF + m;
                acc += in[idx] * w[((kd*3 + kh)*3 + kw) * MFF + m];
            }
        }
    }
    // exact gelu: 0.5*x*(1+erf(x/sqrt(2)))
    out[e] = 0.5f * acc * (1.0f + erff(acc * 0.7071067811865475f));
}

// ---------------- host launcher ----------------
static float* devptr(const void* symAddr) { return (float*)symAddr; }

extern "C" void kernel_launch(void* const* d_in, const int* in_sizes, int n_in,
                              void* d_out, int out_size)
{
    const float* x      = (const float*)d_in[0];
    const float* ln1_g  = (const float*)d_in[1];
    const float* ln1_b  = (const float*)d_in[2];
    const float* qkv_w  = (const float*)d_in[3];
    const float* qkv_b  = (const float*)d_in[4];
    const float* rpb    = (const float*)d_in[5];
    const float* proj_w = (const float*)d_in[6];
    const float* proj_b = (const float*)d_in[7];
    const float* ln2_g  = (const float*)d_in[8];
    const float* ln2_b  = (const float*)d_in[9];
    const float* fc1_w  = (const float*)d_in[10];
    const float* fc1_b  = (const float*)d_in[11];
    const float* dw_w   = (const float*)d_in[12];
    const float* dw_b   = (const float*)d_in[13];
    const float* fc2_w  = (const float*)d_in[14];
    const float* fc2_b  = (const float*)d_in[15];
    const float* out_g  = (const float*)d_in[16];
    const float* out_b  = (const float*)d_in[17];
    float* out = (float*)d_out;

    static float *p_h=nullptr,*p_ln,*p_qkv,*p_att,*p_f1,*p_f2;
    if (!p_h) {
        cudaGetSymbolAddress((void**)&p_h,   g_h);
        cudaGetSymbolAddress((void**)&p_ln,  g_ln);
        cudaGetSymbolAddress((void**)&p_qkv, g_qkv);
        cudaGetSymbolAddress((void**)&p_att, g_att);
        cudaGetSymbolAddress((void**)&p_f1,  g_f1);
        cudaGetSymbolAddress((void**)&p_f2,  g_f2);
    }

    dim3 tposeGrid(SPA/32, CC/32, 2);
    dim3 tposeBlk(32, 8);
    dim3 gemmBlk(16, 16);

    k_transpose_in<<<tposeGrid, tposeBlk>>>(x, p_h);

    for (int l = 0; l < 2; l++) {
        // --- attention sub-block ---
        k_layernorm<<<NTOK, 128>>>(p_h, ln1_g + l*CC, ln1_b + l*CC, p_ln);
        k_sgemm<false><<<dim3(384/64, NTOK/64), gemmBlk>>>(
            p_ln, qkv_w + (size_t)l*CC*384, qkv_b + l*384, nullptr, p_qkv,
            NTOK, 384, CC);
        k_attn<<<NTOK, 128>>>(p_qkv, rpb + l*HEADS*13*13, p_att);
        k_sgemm<true><<<dim3(CC/64, NTOK/64), gemmBlk>>>(
            p_att, proj_w + (size_t)l*CC*CC, proj_b + l*CC, p_h, p_h,
            NTOK, CC, CC);

        // --- mixffn sub-block ---
        k_layernorm<<<NTOK, 128>>>(p_h, ln2_g + l*CC, ln2_b + l*CC, p_ln);
        k_sgemm<false><<<dim3(MFF/64, NTOK/64), gemmBlk>>>(
            p_ln, fc1_w + (size_t)l*CC*MFF, fc1_b + l*MFF, nullptr, p_f1,
            NTOK, MFF, CC);
        k_dwconv_gelu<<<(NTOK*MFF + 255)/256, 256>>>(
            p_f1, dw_w + (size_t)l*27*MFF, dw_b + l*MFF, p_f2);
        k_sgemm<true><<<dim3(CC/64, NTOK/64), gemmBlk>>>(
            p_f2, fc2_w + (size_t)l*MFF*CC, fc2_b + l*CC, p_h, p_h,
            NTOK, CC, MFF);
    }

    k_layernorm<<<NTOK, 128>>>(p_h, out_g, out_b, p_ln);
    k_transpose_out<<<tposeGrid, tposeBlk>>>(p_ln, out);
}

// round 11
// speedup vs baseline: 1.0019x; 1.0019x over previous
#include <cuda_runtime.h>
#include <math.h>

// ---------------- problem constants ----------------
#define BT    16          // b*t frames
#define HH    40
#define WW    40
#define CC    128
#define NTOK  (BT*HH*WW)  // 25600
#define MFF   512
#define HEADS 4
#define DH    32
#define KNB   7
#define KK2   49
#define SPA   (8*HH*WW)   // 12800 spatial per batch-b

// ---------------- scratch (device globals; no allocations) ----------------
__device__ float g_h   [NTOK*CC];   // running hidden state
__device__ float g_ln  [NTOK*CC];   // layernorm output / staging
__device__ float g_qkv [NTOK*3*CC];
__device__ float g_att [NTOK*CC];
__device__ float g_f1  [NTOK*MFF];
__device__ float g_f2  [NTOK*MFF];

// ---------------- transpose in: x(B=2,C=128,T*H*W=12800) -> h(tok,C) ----------------
__global__ void k_transpose_in(const float* __restrict__ x, float* __restrict__ h)
{
    __shared__ float tile[32][33];
    int b  = blockIdx.z;
    int s0 = blockIdx.x * 32;
    int c0 = blockIdx.y * 32;
    int tx = threadIdx.x, ty = threadIdx.y;
#pragma unroll
    for (int i = 0; i < 32; i += 8)
        tile[ty + i][tx] = x[(size_t)(b*CC + c0 + ty + i) * SPA + s0 + tx];
    __syncthreads();
#pragma unroll
    for (int i = 0; i < 32; i += 8)
        h[(size_t)(b*SPA + s0 + ty + i) * CC + c0 + tx] = tile[tx][ty + i];
}

// ---------------- transpose out: h(tok,C) -> out(B,C,T*H*W) ----------------
__global__ void k_transpose_out(const float* __restrict__ h, float* __restrict__ out)
{
    __shared__ float tile[32][33];
    int b  = blockIdx.z;
    int s0 = blockIdx.x * 32;
    int c0 = blockIdx.y * 32;
    int tx = threadIdx.x, ty = threadIdx.y;
#pragma unroll
    for (int i = 0; i < 32; i += 8)
        tile[ty + i][tx] = h[(size_t)(b*SPA + s0 + ty + i) * CC + c0 + tx];
    __syncthreads();
#pragma unroll
    for (int i = 0; i < 32; i += 8)
        out[(size_t)(b*CC + c0 + ty + i) * SPA + s0 + tx] = tile[tx][ty + i];
}

// ---------------- per-token layernorm over C=128 ----------------
__global__ void k_layernorm(const float* __restrict__ in,
                            const float* __restrict__ g,
                            const float* __restrict__ b,
                            float* __restrict__ out)
{
    int tok = blockIdx.x;
    int c   = threadIdx.x;          // 128 threads
    float v = in[(size_t)tok*CC + c];
    float s = v, q = v*v;
#pragma unroll
    for (int o = 16; o > 0; o >>= 1) {
        s += __shfl_xor_sync(0xffffffffu, s, o);
        q += __shfl_xor_sync(0xffffffffu, q, o);
    }
    __shared__ float sh[8];
    int wid = c >> 5, lane = c & 31;
    if (lane == 0) { sh[wid] = s; sh[4+wid] = q; }
    __syncthreads();
    s = sh[0]+sh[1]+sh[2]+sh[3];
    q = sh[4]+sh[5]+sh[6]+sh[7];
    float mean = s * (1.0f/CC);
    float var  = q * (1.0f/CC) - mean*mean;
    float r    = rsqrtf(var + 1e-5f);
    out[(size_t)tok*CC + c] = (v - mean) * r * g[c] + b[c];
}

// ---------------- SGEMM: C[M,N] = A[M,K] @ B[K,N] + bias (+res) ----------------
// BM=BN=64, BK=16, 256 threads (16x16), 4x4 microtile. M%64==0, N%64==0, K%16==0.
template<bool RES>
__global__ void k_sgemm(const float* __restrict__ A, const float* __restrict__ B,
                        const float* __restrict__ bias, const float* __restrict__ res,
                        float* __restrict__ C, int M, int N, int K)
{
    __shared__ float As[16][65];   // [k][row], padded -> conflict-free stores/reads
    __shared__ float Bs[16][64];   // [k][col]
    int tid  = threadIdx.y * 16 + threadIdx.x;
    int row0 = blockIdx.y * 64;
    int col0 = blockIdx.x * 64;

    int aRow = tid >> 4;     // 0..15
    int aCol = tid & 15;     // 0..15
    int bRow = tid >> 6;     // 0..3
    int bCol = tid & 63;     // 0..63

    float acc[4][4];
#pragma unroll
    for (int i = 0; i < 4; i++)
#pragma unroll
        for (int j = 0; j < 4; j++) acc[i][j] = 0.0f;

    for (int k0 = 0; k0 < K; k0 += 16) {
#pragma unroll
        for (int i = 0; i < 4; i++)
            As[aCol][aRow + i*16] = A[(size_t)(row0 + aRow + i*16) * K + k0 + aCol];
#pragma unroll
        for (int i = 0; i < 4; i++)
            Bs[bRow + i*4][bCol]  = B[(size_t)(k0 + bRow + i*4) * N + col0 + bCol];
        __syncthreads();
#pragma unroll
        for (int kk = 0; kk < 16; kk++) {
            float a[4], bb[4];
#pragma unroll
            for (int i = 0; i < 4; i++) a[i]  = As[kk][threadIdx.y*4 + i];
#pragma unroll
            for (int j = 0; j < 4; j++) bb[j] = Bs[kk][threadIdx.x*4 + j];
#pragma unroll
            for (int i = 0; i < 4; i++)
#pragma unroll
                for (int j = 0; j < 4; j++)
                    acc[i][j] += a[i] * bb[j];
        }
        __syncthreads();
    }
#pragma unroll
    for (int i = 0; i < 4; i++) {
        int r = row0 + threadIdx.y*4 + i;
#pragma unroll
        for (int j = 0; j < 4; j++) {
            int c = col0 + threadIdx.x*4 + j;
            float v = acc[i][j] + bias[c];
            if (RES) v += res[(size_t)r * N + c];
            C[(size_t)r * N + c] = v;
        }
    }
}

// ---------------- neighborhood attention (k=7, heads=4, dh=32) ----------------
// one block per token, one warp per head; lane = head-dim d
__global__ void k_attn(const float* __restrict__ qkv,
                       const float* __restrict__ rpb,   // [4][13][13] for this layer
                       float* __restrict__ out)
{
    int tok  = blockIdx.x;
    int head = threadIdx.x >> 5;
    int lane = threadIdx.x & 31;
    int x  = tok % WW;
    int y  = (tok / WW) % HH;
    int bt = tok / (HH*WW);

    __shared__ float s_log[HEADS][KK2];

    int sy = min(max(y - 3, 0), HH - KNB);
    int sx = min(max(x - 3, 0), WW - KNB);

    float q = qkv[(size_t)tok*384 + head*DH + lane] * 0.17677669529663687f; // dh^-0.5

    // logits
    for (int i = 0; i < KNB; i++) {
        int iy = sy + i;
        int rowbase = (bt*HH + iy) * WW;
        int rh = iy - y + 6;
#pragma unroll
        for (int j = 0; j < KNB; j++) {
            int ix = sx + j;
            int kt = rowbase + ix;
            float p = q * qkv[(size_t)kt*384 + CC + head*DH + lane];
#pragma unroll
            for (int o = 16; o > 0; o >>= 1) p += __shfl_xor_sync(0xffffffffu, p, o);
            if (lane == 0) {
                float bias = rpb[(head*13 + rh)*13 + (ix - x + 6)];
                s_log[head][i*KNB + j] = p + bias;
            }
        }
    }
    __syncwarp();

    // softmax over 49 (each lane handles j and j+32)
    float l0 = s_log[head][lane];
    float l1 = (lane + 32 < KK2) ? s_log[head][lane + 32] : -1e30f;
    float m = fmaxf(l0, l1);
#pragma unroll
    for (int o = 16; o > 0; o >>= 1) m = fmaxf(m, __shfl_xor_sync(0xffffffffu, m, o));
    float e0 = expf(l0 - m);
    float e1 = (lane + 32 < KK2) ? expf(l1 - m) : 0.0f;
    float s = e0 + e1;
#pragma unroll
    for (int o = 16; o > 0; o >>= 1) s += __shfl_xor_sync(0xffffffffu, s, o);
    float inv = 1.0f / s;
    s_log[head][lane] = e0 * inv;
    if (lane + 32 < KK2) s_log[head][lane + 32] = e1 * inv;
    __syncwarp();

    // weighted sum over v
    float acc = 0.0f;
    for (int i = 0; i < KNB; i++) {
        int rowbase = (bt*HH + sy + i) * WW;
#pragma unroll
        for (int j = 0; j < KNB; j++) {
            int kt = rowbase + sx + j;
            acc += s_log[head][i*KNB + j] * qkv[(size_t)kt*384 + 2*CC + head*DH + lane];
        }
    }
    out[(size_t)tok*CC + head*DH + lane] = acc;
}

// ---------------- depthwise 3x3x3 conv (SAME, over t,y,x) + exact GELU ----------------
__global__ void k_dwconv_gelu(const float* __restrict__ in,
                              const float* __restrict__ w,    // [3][3][3][1][512]
                              const float* __restrict__ bias, // [512]
                              float* __restrict__ out)
{
    int e = blockIdx.x * blockDim.x + threadIdx.x;
    if (e >= NTOK * MFF) return;
    int m   = e & (MFF - 1);
    int tok = e >> 9;
    int x  = tok % WW;
    int y  = (tok / WW) % HH;
    int bt = tok / (HH*WW);
    int b  = bt >> 3;
    int t  = bt & 7;

    float acc = bias[m];
#pragma unroll
    for (int kd = 0; kd < 3; kd++) {
        int tt = t + kd - 1;
        if (tt < 0 || tt > 7) continue;
#pragma unroll
        for (int kh = 0; kh < 3; kh++) {
            int yy = y + kh - 1;
            if (yy < 0 || yy >= HH) continue;
#pragma unroll
            for (int kw = 0; kw < 3; kw++) {
                int xx = x + kw - 1;
                if (xx < 0 || xx >= WW) continue;
                size_t idx = ((size_t)((b*8 + tt)*HH + yy) * WW + xx) * MFF + m;
                acc += in[idx] * w[((kd*3 + kh)*3 + kw) * MFF + m];
            }
        }
    }
    // exact gelu: 0.5*x*(1+erf(x/sqrt(2)))
    out[e] = 0.5f * acc * (1.0f + erff(acc * 0.7071067811865475f));
}

// ---------------- host launcher ----------------
static float* devptr(const void* symAddr) { return (float*)symAddr; }

extern "C" void kernel_launch(void* const* d_in, const int* in_sizes, int n_in,
                              void* d_out, int out_size)
{
    const float* x      = (const float*)d_in[0];
    const float* ln1_g  = (const float*)d_in[1];
    const float* ln1_b  = (const float*)d_in[2];
    const float* qkv_w  = (const float*)d_in[3];
    const float* qkv_b  = (const float*)d_in[4];
    const float* rpb    = (const float*)d_in[5];
    const float* proj_w = (const float*)d_in[6];
    const float* proj_b = (const float*)d_in[7];
    const float* ln2_g  = (const float*)d_in[8];
    const float* ln2_b  = (const float*)d_in[9];
    const float* fc1_w  = (const float*)d_in[10];
    const float* fc1_b  = (const float*)d_in[11];
    const float* dw_w   = (const float*)d_in[12];
    const float* dw_b   = (const float*)d_in[13];
    const float* fc2_w  = (const float*)d_in[14];
    const float* fc2_b  = (const float*)d_in[15];
    const float* out_g  = (const float*)d_in[16];
    const float* out_b  = (const float*)d_in[17];
    float* out = (float*)d_out;

    static float *p_h=nullptr,*p_ln,*p_qkv,*p_att,*p_f1,*p_f2;
    if (!p_h) {
        cudaGetSymbolAddress((void**)&p_h,   g_h);
        cudaGetSymbolAddress((void**)&p_ln,  g_ln);
        cudaGetSymbolAddress((void**)&p_qkv, g_qkv);
        cudaGetSymbolAddress((void**)&p_att, g_att);
        cudaGetSymbolAddress((void**)&p_f1,  g_f1);
        cudaGetSymbolAddress((void**)&p_f2,  g_f2);
    }

    dim3 tposeGrid(SPA/32, CC/32, 2);
    dim3 tposeBlk(32, 8);
    dim3 gemmBlk(16, 16);

    k_transpose_in<<<tposeGrid, tposeBlk>>>(x, p_h);

    for (int l = 0; l < 2; l++) {
        // --- attention sub-block ---
        k_layernorm<<<NTOK, 128>>>(p_h, ln1_g + l*CC, ln1_b + l*CC, p_ln);
        k_sgemm<false><<<dim3(384/64, NTOK/64), gemmBlk>>>(
            p_ln, qkv_w + (size_t)l*CC*384, qkv_b + l*384, nullptr, p_qkv,
            NTOK, 384, CC);
        k_attn<<<NTOK, 128>>>(p_qkv, rpb + l*HEADS*13*13, p_att);
        k_sgemm<true><<<dim3(CC/64, NTOK/64), gemmBlk>>>(
            p_att, proj_w + (size_t)l*CC*CC, proj_b + l*CC, p_h, p_h,
            NTOK, CC, CC);

        // --- mixffn sub-block ---
        k_layernorm<<<NTOK, 128>>>(p_h, ln2_g + l*CC, ln2_b + l*CC, p_ln);
        k_sgemm<false><<<dim3(MFF/64, NTOK/64), gemmBlk>>>(
            p_ln, fc1_w + (size_t)l*CC*MFF, fc1_b + l*MFF, nullptr, p_f1,
            NTOK, MFF, CC);
        k_dwconv_gelu<<<(NTOK*MFF + 255)/256, 256>>>(
            p_f1, dw_w + (size_t)l*27*MFF, dw_b + l*MFF, p_f2);
        k_sgemm<true><<<dim3(CC/64, NTOK/64), gemmBlk>>>(
            p_f2, fc2_w + (size_t)l*MFF*CC, fc2_b + l*CC, p_h, p_h,
            NTOK, CC, MFF);
    }

    k_layernorm<<<NTOK, 128>>>(p_h, out_g, out_b, p_ln);
    k_transpose_out<<<tposeGrid, tposeBlk>>>(p_ln, out);
}

// round 12
// speedup vs baseline: 1.0027x; 1.0009x over previous
#include <cuda_runtime.h>
#include <math.h>

// ---------------- problem constants ----------------
#define BT    16          // b*t frames
#define HH    40
#define WW    40
#define CC    128
#define NTOK  (BT*HH*WW)  // 25600
#define MFF   512
#define HEADS 4
#define DH    32
#define KNB   7
#define KK2   49
#define SPA   (8*HH*WW)   // 12800 spatial per batch-b

// ---------------- scratch (device globals; no allocations) ----------------
__device__ float g_h   [NTOK*CC];   // running hidden state
__device__ float g_ln  [NTOK*CC];   // layernorm output / staging
__device__ float g_qkv [NTOK*3*CC];
__device__ float g_att [NTOK*CC];
__device__ float g_f1  [NTOK*MFF];
__device__ float g_f2  [NTOK*MFF];

// ---------------- transpose in: x(B=2,C=128,T*H*W=12800) -> h(tok,C) ----------------
__global__ void k_transpose_in(const float* __restrict__ x, float* __restrict__ h)
{
    __shared__ float tile[32][33];
    int b  = blockIdx.z;
    int s0 = blockIdx.x * 32;
    int c0 = blockIdx.y * 32;
    int tx = threadIdx.x, ty = threadIdx.y;
#pragma unroll
    for (int i = 0; i < 32; i += 8)
        tile[ty + i][tx] = x[(size_t)(b*CC + c0 + ty + i) * SPA + s0 + tx];
    __syncthreads();
#pragma unroll
    for (int i = 0; i < 32; i += 8)
        h[(size_t)(b*SPA + s0 + ty + i) * CC + c0 + tx] = tile[tx][ty + i];
}

// ---------------- transpose out: h(tok,C) -> out(B,C,T*H*W) ----------------
__global__ void k_transpose_out(const float* __restrict__ h, float* __restrict__ out)
{
    __shared__ float tile[32][33];
    int b  = blockIdx.z;
    int s0 = blockIdx.x * 32;
    int c0 = blockIdx.y * 32;
    int tx = threadIdx.x, ty = threadIdx.y;
#pragma unroll
    for (int i = 0; i < 32; i += 8)
        tile[ty + i][tx] = h[(size_t)(b*SPA + s0 + ty + i) * CC + c0 + tx];
    __syncthreads();
#pragma unroll
    for (int i = 0; i < 32; i += 8)
        out[(size_t)(b*CC + c0 + ty + i) * SPA + s0 + tx] = tile[tx][ty + i];
}

// ---------------- per-token layernorm over C=128 ----------------
__global__ void k_layernorm(const float* __restrict__ in,
                            const float* __restrict__ g,
                            const float* __restrict__ b,
                            float* __restrict__ out)
{
    int tok = blockIdx.x;
    int c   = threadIdx.x;          // 128 threads
    float v = in[(size_t)tok*CC + c];
    float s = v, q = v*v;
#pragma unroll
    for (int o = 16; o > 0; o >>= 1) {
        s += __shfl_xor_sync(0xffffffffu, s, o);
        q += __shfl_xor_sync(0xffffffffu, q, o);
    }
    __shared__ float sh[8];
    int wid = c >> 5, lane = c & 31;
    if (lane == 0) { sh[wid] = s; sh[4+wid] = q; }
    __syncthreads();
    s = sh[0]+sh[1]+sh[2]+sh[3];
    q = sh[4]+sh[5]+sh[6]+sh[7];
    float mean = s * (1.0f/CC);
    float var  = q * (1.0f/CC) - mean*mean;
    float r    = rsqrtf(var + 1e-5f);
    out[(size_t)tok*CC + c] = (v - mean) * r * g[c] + b[c];
}

// ---------------- SGEMM: C[M,N] = A[M,K] @ B[K,N] + bias (+res) ----------------
// BM=BN=64, BK=16, 256 threads (16x16), 4x4 microtile. M%64==0, N%64==0, K%16==0.
template<bool RES>
__global__ void k_sgemm(const float* __restrict__ A, const float* __restrict__ B,
                        const float* __restrict__ bias, const float* __restrict__ res,
                        float* __restrict__ C, int M, int N, int K)
{
    __shared__ float As[16][65];   // [k][row], padded -> conflict-free stores/reads
    __shared__ float Bs[16][64];   // [k][col]
    int tid  = threadIdx.y * 16 + threadIdx.x;
    int row0 = blockIdx.y * 64;
    int col0 = blockIdx.x * 64;

    int aRow = tid >> 4;     // 0..15
    int aCol = tid & 15;     // 0..15
    int bRow = tid >> 6;     // 0..3
    int bCol = tid & 63;     // 0..63

    float acc[4][4];
#pragma unroll
    for (int i = 0; i < 4; i++)
#pragma unroll
        for (int j = 0; j < 4; j++) acc[i][j] = 0.0f;

    for (int k0 = 0; k0 < K; k0 += 16) {
#pragma unroll
        for (int i = 0; i < 4; i++)
            As[aCol][aRow + i*16] = A[(size_t)(row0 + aRow + i*16) * K + k0 + aCol];
#pragma unroll
        for (int i = 0; i < 4; i++)
            Bs[bRow + i*4][bCol]  = B[(size_t)(k0 + bRow + i*4) * N + col0 + bCol];
        __syncthreads();
#pragma unroll
        for (int kk = 0; kk < 16; kk++) {
            float a[4], bb[4];
#pragma unroll
            for (int i = 0; i < 4; i++) a[i]  = As[kk][threadIdx.y*4 + i];
#pragma unroll
            for (int j = 0; j < 4; j++) bb[j] = Bs[kk][threadIdx.x*4 + j];
#pragma unroll
            for (int i = 0; i < 4; i++)
#pragma unroll
                for (int j = 0; j < 4; j++)
                    acc[i][j] += a[i] * bb[j];
        }
        __syncthreads();
    }
#pragma unroll
    for (int i = 0; i < 4; i++) {
        int r = row0 + threadIdx.y*4 + i;
#pragma unroll
        for (int j = 0; j < 4; j++) {
            int c = col0 + threadIdx.x*4 + j;
            float v = acc[i][j] + bias[c];
            if (RES) v += res[(size_t)r * N + c];
            C[(size_t)r * N + c] = v;
        }
    }
}

// ---------------- neighborhood attention (k=7, heads=4, dh=32) ----------------
// one block per token, one warp per head; lane = head-dim d
__global__ void k_attn(const float* __restrict__ qkv,
                       const float* __restrict__ rpb,   // [4][13][13] for this layer
                       float* __restrict__ out)
{
    int tok  = blockIdx.x;
    int head = threadIdx.x >> 5;
    int lane = threadIdx.x & 31;
    int x  = tok % WW;
    int y  = (tok / WW) % HH;
    int bt = tok / (HH*WW);

    __shared__ float s_log[HEADS][KK2];

    int sy = min(max(y - 3, 0), HH - KNB);
    int sx = min(max(x - 3, 0), WW - KNB);

    float q = qkv[(size_t)tok*384 + head*DH + lane] * 0.17677669529663687f; // dh^-0.5

    // logits
    for (int i = 0; i < KNB; i++) {
        int iy = sy + i;
        int rowbase = (bt*HH + iy) * WW;
        int rh = iy - y + 6;
#pragma unroll
        for (int j = 0; j < KNB; j++) {
            int ix = sx + j;
            int kt = rowbase + ix;
            float p = q * qkv[(size_t)kt*384 + CC + head*DH + lane];
#pragma unroll
            for (int o = 16; o > 0; o >>= 1) p += __shfl_xor_sync(0xffffffffu, p, o);
            if (lane == 0) {
                float bias = rpb[(head*13 + rh)*13 + (ix - x + 6)];
                s_log[head][i*KNB + j] = p + bias;
            }
        }
    }
    __syncwarp();

    // softmax over 49 (each lane handles j and j+32)
    float l0 = s_log[head][lane];
    float l1 = (lane + 32 < KK2) ? s_log[head][lane + 32] : -1e30f;
    float m = fmaxf(l0, l1);
#pragma unroll
    for (int o = 16; o > 0; o >>= 1) m = fmaxf(m, __shfl_xor_sync(0xffffffffu, m, o));
    float e0 = expf(l0 - m);
    float e1 = (lane + 32 < KK2) ? expf(l1 - m) : 0.0f;
    float s = e0 + e1;
#pragma unroll
    for (int o = 16; o > 0; o >>= 1) s += __shfl_xor_sync(0xffffffffu, s, o);
    float inv = 1.0f / s;
    s_log[head][lane] = e0 * inv;
    if (lane + 32 < KK2) s_log[head][lane + 32] = e1 * inv;
    __syncwarp();

    // weighted sum over v
    float acc = 0.0f;
    for (int i = 0; i < KNB; i++) {
        int rowbase = (bt*HH + sy + i) * WW;
#pragma unroll
        for (int j = 0; j < KNB; j++) {
            int kt = rowbase + sx + j;
            acc += s_log[head][i*KNB + j] * qkv[(size_t)kt*384 + 2*CC + head*DH + lane];
        }
    }
    out[(size_t)tok*CC + head*DH + lane] = acc;
}

// ---------------- depthwise 3x3x3 conv (SAME, over t,y,x) + exact GELU ----------------
__global__ void k_dwconv_gelu(const float* __restrict__ in,
                              const float* __restrict__ w,    // [3][3][3][1][512]
                              const float* __restrict__ bias, // [512]
                              float* __restrict__ out)
{
    int e = blockIdx.x * blockDim.x + threadIdx.x;
    if (e >= NTOK * MFF) return;
    int m   = e & (MFF - 1);
    int tok = e >> 9;
    int x  = tok % WW;
    int y  = (tok / WW) % HH;
    int bt = tok / (HH*WW);
    int b  = bt >> 3;
    int t  = bt & 7;

    float acc = bias[m];
#pragma unroll
    for (int kd = 0; kd < 3; kd++) {
        int tt = t + kd - 1;
        if (tt < 0 || tt > 7) continue;
#pragma unroll
        for (int kh = 0; kh < 3; kh++) {
            int yy = y + kh - 1;
            if (yy < 0 || yy >= HH) continue;
#pragma unroll
            for (int kw = 0; kw < 3; kw++) {
                int xx = x + kw - 1;
                if (xx < 0 || xx >= WW) continue;
                size_t idx = ((size_t)((b*8 + tt)*HH + yy) * WW + xx) * MFF + m;
                acc += in[idx] * w[((kd*3 + kh)*3 + kw) * MFF + m];
            }
        }
    }
    // exact gelu: 0.5*x*(1+erf(x/sqrt(2)))
    out[e] = 0.5f * acc * (1.0f + erff(acc * 0.7071067811865475f));
}

// ---------------- host launcher ----------------
static float* devptr(const void* symAddr) { return (float*)symAddr; }

extern "C" void kernel_launch(void* const* d_in, const int* in_sizes, int n_in,
                              void* d_out, int out_size)
{
    const float* x      = (const float*)d_in[0];
    const float* ln1_g  = (const float*)d_in[1];
    const float* ln1_b  = (const float*)d_in[2];
    const float* qkv_w  = (const float*)d_in[3];
    const float* qkv_b  = (const float*)d_in[4];
    const float* rpb    = (const float*)d_in[5];
    const float* proj_w = (const float*)d_in[6];
    const float* proj_b = (const float*)d_in[7];
    const float* ln2_g  = (const float*)d_in[8];
    const float* ln2_b  = (const float*)d_in[9];
    const float* fc1_w  = (const float*)d_in[10];
    const float* fc1_b  = (const float*)d_in[11];
    const float* dw_w   = (const float*)d_in[12];
    const float* dw_b   = (const float*)d_in[13];
    const float* fc2_w  = (const float*)d_in[14];
    const float* fc2_b  = (const float*)d_in[15];
    const float* out_g  = (const float*)d_in[16];
    const float* out_b  = (const float*)d_in[17];
    float* out = (float*)d_out;

    static float *p_h=nullptr,*p_ln,*p_qkv,*p_att,*p_f1,*p_f2;
    if (!p_h) {
        cudaGetSymbolAddress((void**)&p_h,   g_h);
        cudaGetSymbolAddress((void**)&p_ln,  g_ln);
        cudaGetSymbolAddress((void**)&p_qkv, g_qkv);
        cudaGetSymbolAddress((void**)&p_att, g_att);
        cudaGetSymbolAddress((void**)&p_f1,  g_f1);
        cudaGetSymbolAddress((void**)&p_f2,  g_f2);
    }

    dim3 tposeGrid(SPA/32, CC/32, 2);
    dim3 tposeBlk(32, 8);
    dim3 gemmBlk(16, 16);

    k_transpose_in<<<tposeGrid, tposeBlk>>>(x, p_h);

    for (int l = 0; l < 2; l++) {
        // --- attention sub-block ---
        k_layernorm<<<NTOK, 128>>>(p_h, ln1_g + l*CC, ln1_b + l*CC, p_ln);
        k_sgemm<false><<<dim3(384/64, NTOK/64), gemmBlk>>>(
            p_ln, qkv_w + (size_t)l*CC*384, qkv_b + l*384, nullptr, p_qkv,
            NTOK, 384, CC);
        k_attn<<<NTOK, 128>>>(p_qkv, rpb + l*HEADS*13*13, p_att);
        k_sgemm<true><<<dim3(CC/64, NTOK/64), gemmBlk>>>(
            p_att, proj_w + (size_t)l*CC*CC, proj_b + l*CC, p_h, p_h,
            NTOK, CC, CC);

        // --- mixffn sub-block ---
        k_layernorm<<<NTOK, 128>>>(p_h, ln2_g + l*CC, ln2_b + l*CC, p_ln);
        k_sgemm<false><<<dim3(MFF/64, NTOK/64), gemmBlk>>>(
            p_ln, fc1_w + (size_t)l*CC*MFF, fc1_b + l*MFF, nullptr, p_f1,
            NTOK, MFF, CC);
        k_dwconv_gelu<<<(NTOK*MFF + 255)/256, 256>>>(
            p_f1, dw_w + (size_t)l*27*MFF, dw_b + l*MFF, p_f2);
        k_sgemm<true><<<dim3(CC/64, NTOK/64), gemmBlk>>>(
            p_f2, fc2_w + (size_t)l*MFF*CC, fc2_b + l*CC, p_h, p_h,
            NTOK, CC, MFF);
    }

    k_layernorm<<<NTOK, 128>>>(p_h, out_g, out_b, p_ln);
    k_transpose_out<<<tposeGrid, tposeBlk>>>(p_ln, out);
}

// round 13
// speedup vs baseline: 1.0872x; 1.0842x over previous
#include <cuda_runtime.h>
#include <math.h>

// ---------------- problem constants ----------------
#define BT    16          // b*t frames
#define HH    40
#define WW    40
#define CC    128
#define NTOK  (BT*HH*WW)  // 25600
#define MFF   512
#define HEADS 4
#define DH    32
#define KNB   7
#define KK2   49
#define SPA   (8*HH*WW)   // 12800 spatial per batch-b

// ---------------- scratch (device globals; no allocations) ----------------
__device__ float g_h   [NTOK*CC];   // running hidden state
__device__ float g_ln  [NTOK*CC];   // layernorm output / staging
__device__ float g_qkv [NTOK*3*CC];
__device__ float g_att [NTOK*CC];
__device__ float g_f1  [NTOK*MFF];
__device__ float g_f2  [NTOK*MFF];

// ---------------- transpose in: x(B=2,C=128,T*H*W=12800) -> h(tok,C) ----------------
__global__ void k_transpose_in(const float* __restrict__ x, float* __restrict__ h)
{
    __shared__ float tile[32][33];
    int b  = blockIdx.z;
    int s0 = blockIdx.x * 32;
    int c0 = blockIdx.y * 32;
    int tx = threadIdx.x, ty = threadIdx.y;
#pragma unroll
    for (int i = 0; i < 32; i += 8)
        tile[ty + i][tx] = x[(size_t)(b*CC + c0 + ty + i) * SPA + s0 + tx];
    __syncthreads();
#pragma unroll
    for (int i = 0; i < 32; i += 8)
        h[(size_t)(b*SPA + s0 + ty + i) * CC + c0 + tx] = tile[tx][ty + i];
}

// ---------------- transpose out: h(tok,C) -> out(B,C,T*H*W) ----------------
__global__ void k_transpose_out(const float* __restrict__ h, float* __restrict__ out)
{
    __shared__ float tile[32][33];
    int b  = blockIdx.z;
    int s0 = blockIdx.x * 32;
    int c0 = blockIdx.y * 32;
    int tx = threadIdx.x, ty = threadIdx.y;
#pragma unroll
    for (int i = 0; i < 32; i += 8)
        tile[ty + i][tx] = h[(size_t)(b*SPA + s0 + ty + i) * CC + c0 + tx];
    __syncthreads();
#pragma unroll
    for (int i = 0; i < 32; i += 8)
        out[(size_t)(b*CC + c0 + ty + i) * SPA + s0 + tx] = tile[tx][ty + i];
}

// ---------------- per-token layernorm over C=128 ----------------
__global__ void k_layernorm(const float* __restrict__ in,
                            const float* __restrict__ g,
                            const float* __restrict__ b,
                            float* __restrict__ out)
{
    int tok = blockIdx.x;
    int c   = threadIdx.x;          // 128 threads
    float v = in[(size_t)tok*CC + c];
    float s = v, q = v*v;
#pragma unroll
    for (int o = 16; o > 0; o >>= 1) {
        s += __shfl_xor_sync(0xffffffffu, s, o);
        q += __shfl_xor_sync(0xffffffffu, q, o);
    }
    __shared__ float sh[8];
    int wid = c >> 5, lane = c & 31;
    if (lane == 0) { sh[wid] = s; sh[4+wid] = q; }
    __syncthreads();
    s = sh[0]+sh[1]+sh[2]+sh[3];
    q = sh[4]+sh[5]+sh[6]+sh[7];
    float mean = s * (1.0f/CC);
    float var  = q * (1.0f/CC) - mean*mean;
    float r    = rsqrtf(var + 1e-5f);
    out[(size_t)tok*CC + c] = (v - mean) * r * g[c] + b[c];
}

// ---------------- SGEMM v2: C[M,N] = A[M,K] @ B[K,N] + bias (+res) ----------------
// BN=128 fixed, BK=16, 256 threads. BM=128 (TM=8) or BM=64 (TM=4), TN=8.
// Double-buffered smem, register-staged prefetch, float4 everywhere.
// Requires: M%BM==0, N%128==0, K%16==0.
template<int BM, int TM, bool RES>
__global__ __launch_bounds__(256)
void k_sgemm2(const float* __restrict__ A, const float* __restrict__ B,
              const float* __restrict__ bias, const float* __restrict__ res,
              float* __restrict__ C, int M, int N, int K)
{
    constexpr int BN = 128;
    constexpr int BK = 16;
    constexpr int TN = 8;
    constexpr int PBM = BM + 4;            // pad keeps rows 16B-aligned (BM%4==0)
    constexpr int NA = BM / 64;            // float4 A-loads per thread (1 or 2)

    __shared__ __align__(16) float As[2][BK][PBM];  // [k][row]
    __shared__ __align__(16) float Bs[2][BK][BN];   // [k][col]

    const int tid = threadIdx.x;
    const int tx  = tid & 15;              // 0..15 -> 8 cols (two float4)
    const int ty  = tid >> 4;              // 0..15 -> TM rows
    const int row0 = blockIdx.y * BM;
    const int col0 = blockIdx.x * BN;

    float4 pa[NA], pb[2];

    // ---- global -> regs ----
    auto loadA = [&](int k0) {
#pragma unroll
        for (int p = 0; p < NA; p++) {
            int id  = tid + p * 256;
            int row = id >> 2;             // 0..BM-1
            int kq  = id & 3;              // 0..3 (float4 along K)
            pa[p] = *(const float4*)&A[(size_t)(row0 + row) * K + k0 + kq * 4];
        }
    };
    auto loadB = [&](int k0) {
#pragma unroll
        for (int p = 0; p < 2; p++) {
            int id = tid + p * 256;
            int kr = id >> 5;              // 0..15
            int cq = id & 31;              // 0..31 -> col = cq*4
            pb[p] = *(const float4*)&B[(size_t)(k0 + kr) * N + col0 + cq * 4];
        }
    };
    // ---- regs -> smem ----
    auto storeA = [&](int buf) {
#pragma unroll
        for (int p = 0; p < NA; p++) {
            int id  = tid + p * 256;
            int row = id >> 2;
            int kq  = id & 3;
            As[buf][kq*4 + 0][row] = pa[p].x;
            As[buf][kq*4 + 1][row] = pa[p].y;
            As[buf][kq*4 + 2][row] = pa[p].z;
            As[buf][kq*4 + 3][row] = pa[p].w;
        }
    };
    auto storeB = [&](int buf) {
#pragma unroll
        for (int p = 0; p < 2; p++) {
            int id = tid + p * 256;
            int kr = id >> 5;
            int cq = id & 31;
            *(float4*)&Bs[buf][kr][cq * 4] = pb[p];
        }
    };

    float acc[TM][TN];
#pragma unroll
    for (int i = 0; i < TM; i++)
#pragma unroll
        for (int j = 0; j < TN; j++) acc[i][j] = 0.0f;

    loadA(0); loadB(0);
    storeA(0); storeB(0);
    __syncthreads();

    const int nk = K / BK;
    int cur = 0;
    for (int t = 0; t < nk; t++) {
        if (t + 1 < nk) { loadA((t + 1) * BK); loadB((t + 1) * BK); }

#pragma unroll
        for (int kk = 0; kk < BK; kk++) {
            float a[TM], b[TN];
            *(float4*)&a[0] = *(const float4*)&As[cur][kk][ty * 4];
            if constexpr (TM == 8)
                *(float4*)&a[4] = *(const float4*)&As[cur][kk][64 + ty * 4];
            *(float4*)&b[0] = *(const float4*)&Bs[cur][kk][tx * 4];
            *(float4*)&b[4] = *(const float4*)&Bs[cur][kk][64 + tx * 4];
#pragma unroll
            for (int i = 0; i < TM; i++)
#pragma unroll
                for (int j = 0; j < TN; j++)
                    acc[i][j] += a[i] * b[j];
        }

        if (t + 1 < nk) {
            storeA(cur ^ 1); storeB(cur ^ 1);
            __syncthreads();
            cur ^= 1;
        }
    }

    // ---- epilogue: bias (+res), float4 stores ----
#pragma unroll
    for (int i = 0; i < TM; i++) {
        int r;
        if constexpr (TM == 8) r = row0 + ((i < 4) ? (ty*4 + i) : (64 + ty*4 + i - 4));
        else                   r = row0 + ty*4 + i;
#pragma unroll
        for (int jq = 0; jq < 2; jq++) {
            int c = col0 + jq*64 + tx*4;
            float4 bv = *(const float4*)&bias[c];
            float4 o;
            o.x = acc[i][jq*4 + 0] + bv.x;
            o.y = acc[i][jq*4 + 1] + bv.y;
            o.z = acc[i][jq*4 + 2] + bv.z;
            o.w = acc[i][jq*4 + 3] + bv.w;
            if (RES) {
                float4 rv = *(const float4*)&res[(size_t)r * N + c];
                o.x += rv.x; o.y += rv.y; o.z += rv.z; o.w += rv.w;
            }
            *(float4*)&C[(size_t)r * N + c] = o;
        }
    }
}

// ---------------- neighborhood attention (k=7, heads=4, dh=32) ----------------
// one block per token, one warp per head; lane = head-dim d
__global__ void k_attn(const float* __restrict__ qkv,
                       const float* __restrict__ rpb,   // [4][13][13] for this layer
                       float* __restrict__ out)
{
    int tok  = blockIdx.x;
    int head = threadIdx.x >> 5;
    int lane = threadIdx.x & 31;
    int x  = tok % WW;
    int y  = (tok / WW) % HH;
    int bt = tok / (HH*WW);

    __shared__ float s_log[HEADS][KK2];

    int sy = min(max(y - 3, 0), HH - KNB);
    int sx = min(max(x - 3, 0), WW - KNB);

    float q = qkv[(size_t)tok*384 + head*DH + lane] * 0.17677669529663687f; // dh^-0.5

    // logits
    for (int i = 0; i < KNB; i++) {
        int iy = sy + i;
        int rowbase = (bt*HH + iy) * WW;
        int rh = iy - y + 6;
#pragma unroll
        for (int j = 0; j < KNB; j++) {
            int ix = sx + j;
            int kt = rowbase + ix;
            float p = q * qkv[(size_t)kt*384 + CC + head*DH + lane];
#pragma unroll
            for (int o = 16; o > 0; o >>= 1) p += __shfl_xor_sync(0xffffffffu, p, o);
            if (lane == 0) {
                float bias = rpb[(head*13 + rh)*13 + (ix - x + 6)];
                s_log[head][i*KNB + j] = p + bias;
            }
        }
    }
    __syncwarp();

    // softmax over 49 (each lane handles j and j+32)
    float l0 = s_log[head][lane];
    float l1 = (lane + 32 < KK2) ? s_log[head][lane + 32] : -1e30f;
    float m = fmaxf(l0, l1);
#pragma unroll
    for (int o = 16; o > 0; o >>= 1) m = fmaxf(m, __shfl_xor_sync(0xffffffffu, m, o));
    float e0 = expf(l0 - m);
    float e1 = (lane + 32 < KK2) ? expf(l1 - m) : 0.0f;
    float s = e0 + e1;
#pragma unroll
    for (int o = 16; o > 0; o >>= 1) s += __shfl_xor_sync(0xffffffffu, s, o);
    float inv = 1.0f / s;
    s_log[head][lane] = e0 * inv;
    if (lane + 32 < KK2) s_log[head][lane + 32] = e1 * inv;
    __syncwarp();

    // weighted sum over v
    float acc = 0.0f;
    for (int i = 0; i < KNB; i++) {
        int rowbase = (bt*HH + sy + i) * WW;
#pragma unroll
        for (int j = 0; j < KNB; j++) {
            int kt = rowbase + sx + j;
            acc += s_log[head][i*KNB + j] * qkv[(size_t)kt*384 + 2*CC + head*DH + lane];
        }
    }
    out[(size_t)tok*CC + head*DH + lane] = acc;
}

// ---------------- depthwise 3x3x3 conv (SAME, over t,y,x) + exact GELU ----------------
__global__ void k_dwconv_gelu(const float* __restrict__ in,
                              const float* __restrict__ w,    // [3][3][3][1][512]
                              const float* __restrict__ bias, // [512]
                              float* __restrict__ out)
{
    int e = blockIdx.x * blockDim.x + threadIdx.x;
    if (e >= NTOK * MFF) return;
    int m   = e & (MFF - 1);
    int tok = e >> 9;
    int x  = tok % WW;
    int y  = (tok / WW) % HH;
    int bt = tok / (HH*WW);
    int b  = bt >> 3;
    int t  = bt & 7;

    float acc = bias[m];
#pragma unroll
    for (int kd = 0; kd < 3; kd++) {
        int tt = t + kd - 1;
        if (tt < 0 || tt > 7) continue;
#pragma unroll
        for (int kh = 0; kh < 3; kh++) {
            int yy = y + kh - 1;
            if (yy < 0 || yy >= HH) continue;
#pragma unroll
            for (int kw = 0; kw < 3; kw++) {
                int xx = x + kw - 1;
                if (xx < 0 || xx >= WW) continue;
                size_t idx = ((size_t)((b*8 + tt)*HH + yy) * WW + xx) * MFF + m;
                acc += in[idx] * w[((kd*3 + kh)*3 + kw) * MFF + m];
            }
        }
    }
    // exact gelu: 0.5*x*(1+erf(x/sqrt(2)))
    out[e] = 0.5f * acc * (1.0f + erff(acc * 0.7071067811865475f));
}

// ---------------- host launcher ----------------
extern "C" void kernel_launch(void* const* d_in, const int* in_sizes, int n_in,
                              void* d_out, int out_size)
{
    const float* x      = (const float*)d_in[0];
    const float* ln1_g  = (const float*)d_in[1];
    const float* ln1_b  = (const float*)d_in[2];
    const float* qkv_w  = (const float*)d_in[3];
    const float* qkv_b  = (const float*)d_in[4];
    const float* rpb    = (const float*)d_in[5];
    const float* proj_w = (const float*)d_in[6];
    const float* proj_b = (const float*)d_in[7];
    const float* ln2_g  = (const float*)d_in[8];
    const float* ln2_b  = (const float*)d_in[9];
    const float* fc1_w  = (const float*)d_in[10];
    const float* fc1_b  = (const float*)d_in[11];
    const float* dw_w   = (const float*)d_in[12];
    const float* dw_b   = (const float*)d_in[13];
    const float* fc2_w  = (const float*)d_in[14];
    const float* fc2_b  = (const float*)d_in[15];
    const float* out_g  = (const float*)d_in[16];
    const float* out_b  = (const float*)d_in[17];
    float* out = (float*)d_out;

    static float *p_h=nullptr,*p_ln,*p_qkv,*p_att,*p_f1,*p_f2;
    if (!p_h) {
        cudaGetSymbolAddress((void**)&p_h,   g_h);
        cudaGetSymbolAddress((void**)&p_ln,  g_ln);
        cudaGetSymbolAddress((void**)&p_qkv, g_qkv);
        cudaGetSymbolAddress((void**)&p_att, g_att);
        cudaGetSymbolAddress((void**)&p_f1,  g_f1);
        cudaGetSymbolAddress((void**)&p_f2,  g_f2);
    }

    dim3 tposeGrid(SPA/32, CC/32, 2);
    dim3 tposeBlk(32, 8);

    k_transpose_in<<<tposeGrid, tposeBlk>>>(x, p_h);

    for (int l = 0; l < 2; l++) {
        // --- attention sub-block ---
        k_layernorm<<<NTOK, 128>>>(p_h, ln1_g + l*CC, ln1_b + l*CC, p_ln);
        // qkv: [25600,128] @ [128,384]   (BM=128, BN=128 -> 200x3 blocks)
        k_sgemm2<128, 8, false><<<dim3(384/128, NTOK/128), 256>>>(
            p_ln, qkv_w + (size_t)l*CC*384, qkv_b + l*384, nullptr, p_qkv,
            NTOK, 384, CC);
        k_attn<<<NTOK, 128>>>(p_qkv, rpb + l*HEADS*13*13, p_att);
        // proj: [25600,128] @ [128,128] + residual  (BM=64 -> 400 blocks)
        k_sgemm2<64, 4, true><<<dim3(CC/128, NTOK/64), 256>>>(
            p_att, proj_w + (size_t)l*CC*CC, proj_b + l*CC, p_h, p_h,
            NTOK, CC, CC);

        // --- mixffn sub-block ---
        k_layernorm<<<NTOK, 128>>>(p_h, ln2_g + l*CC, ln2_b + l*CC, p_ln);
        // fc1: [25600,128] @ [128,512]
        k_sgemm2<128, 8, false><<<dim3(MFF/128, NTOK/128), 256>>>(
            p_ln, fc1_w + (size_t)l*CC*MFF, fc1_b + l*MFF, nullptr, p_f1,
            NTOK, MFF, CC);
        k_dwconv_gelu<<<(NTOK*MFF + 255)/256, 256>>>(
            p_f1, dw_w + (size_t)l*27*MFF, dw_b + l*MFF, p_f2);
        // fc2: [25600,512] @ [512,128] + residual  (BM=64 -> 400 blocks)
        k_sgemm2<64, 4, true><<<dim3(CC/128, NTOK/64), 256>>>(
            p_f2, fc2_w + (size_t)l*MFF*CC, fc2_b + l*CC, p_h, p_h,
            NTOK, CC, MFF);
    }

    k_layernorm<<<NTOK, 128>>>(p_h, out_g, out_b, p_ln);
    k_transpose_out<<<tposeGrid, tposeBlk>>>(p_ln, out);
}